// round 1
// baseline (speedup 1.0000x reference)
#include <cuda_runtime.h>
#include <cstdint>

// PlaneModel: B=8192, NV=8 (512 voxels), P=64, NS=32, HID1=16, BASE=32, OUT=13, D_IN=79
#define FULL 0xffffffffu

typedef unsigned long long u64;

__device__ __forceinline__ u64 dup2(float a){
    u64 r; asm("mov.b64 %0,{%1,%1};" : "=l"(r) : "f"(a)); return r;
}
__device__ __forceinline__ void upk2(u64 v, float& a, float& b){
    asm("mov.b64 {%0,%1},%2;" : "=f"(a), "=f"(b) : "l"(v));
}
__device__ __forceinline__ void fma2(u64& d, u64 a, u64 b){
    asm("fma.rn.f32x2 %0,%1,%2,%0;" : "+l"(d) : "l"(a), "l"(b));
}

__device__ __forceinline__ float wsum(float x){
    x += __shfl_xor_sync(FULL, x, 16);
    x += __shfl_xor_sync(FULL, x, 8);
    x += __shfl_xor_sync(FULL, x, 4);
    x += __shfl_xor_sync(FULL, x, 2);
    x += __shfl_xor_sync(FULL, x, 1);
    return x;
}

// h[8] packed f32x2 accumulators += x * w1row[0..15]
__device__ __forceinline__ void acc_row(u64* h, float x, const float* wrow){
    u64 xx = dup2(x);
    const ulonglong2* w = (const ulonglong2*)wrow;   // 4 x LDS.128 broadcast
    #pragma unroll
    for (int t = 0; t < 4; t++){
        ulonglong2 wv = w[t];
        fma2(h[2*t],   xx, wv.x);
        fma2(h[2*t+1], xx, wv.y);
    }
}

__global__ void __launch_bounds__(128)
plane_kernel(const float* __restrict__ g_pos,  const float* __restrict__ g_quat,
             const float* __restrict__ g_xz,   const float* __restrict__ g_aabb,
             const int*   __restrict__ g_widx, const float* __restrict__ g_pls,
             const float* __restrict__ g_w1,   const float* __restrict__ g_b1,
             const float* __restrict__ g_g1,   const float* __restrict__ g_be1,
             const float* __restrict__ g_w2a,  const float* __restrict__ g_b2a,
             const float* __restrict__ g_g2a,  const float* __restrict__ g_be2a,
             const float* __restrict__ g_w2b,  const float* __restrict__ g_b2b,
             const float* __restrict__ g_g2b,  const float* __restrict__ g_be2b,
             const float* __restrict__ g_wout, const float* __restrict__ g_bout,
             float* __restrict__ g_out)
{
    __shared__ __align__(16) float s_w1[79*16];
    __shared__ __align__(16) float s_b1[16];
    __shared__ float s_g1[16], s_be1[16];
    __shared__ float s_z[4][32*65];   // 4 warps x (32 rows, stride 65 for bank-conflict-free readback)

    const int tid = threadIdx.x;
    for (int i = tid; i < 79*16; i += 128) s_w1[i] = g_w1[i];
    if (tid < 16){ s_b1[tid] = g_b1[tid]; s_g1[tid] = g_g1[tid]; s_be1[tid] = g_be1[tid]; }
    __syncthreads();

    const int warp = tid >> 5, lane = tid & 31;
    const int b = (blockIdx.x << 2) + warp;
    float* sz = s_z[warp];

    const int idx = __ldg(g_widx + b*32 + lane);

    // ---- cooperative coalesced gather of this warp's 32 rows into smem ----
    const float* xzb = g_xz + ((size_t)b << 15);   // b * 512 * 64
    #pragma unroll
    for (int r = 0; r < 32; r++){
        int ir = __shfl_sync(FULL, idx, r);
        const float* src = xzb + (ir << 6);
        sz[r*65 + lane]      = __ldg(src + lane);
        sz[r*65 + 32 + lane] = __ldg(src + 32 + lane);
    }
    __syncwarp(FULL);

    // ---- quaternion -> rotation matrix (per lane, redundant but cheap) ----
    float qx = __ldg(g_quat + b*4 + 0), qy = __ldg(g_quat + b*4 + 1);
    float qz = __ldg(g_quat + b*4 + 2), qw = __ldg(g_quat + b*4 + 3);
    float rn = rsqrtf(qx*qx + qy*qy + qz*qz + qw*qw);
    qx *= rn; qy *= rn; qz *= rn; qw *= rn;
    float r00 = 1.f - 2.f*(qy*qy + qz*qz), r01 = 2.f*(qx*qy - qz*qw), r02 = 2.f*(qx*qz + qy*qw);
    float r10 = 2.f*(qx*qy + qz*qw), r11 = 1.f - 2.f*(qx*qx + qz*qz), r12 = 2.f*(qy*qz - qx*qw);
    float r20 = 2.f*(qx*qz - qy*qw), r21 = 2.f*(qy*qz + qx*qw), r22 = 1.f - 2.f*(qx*qx + qy*qy);

    float px = __ldg(g_pos + b*3 + 0), py = __ldg(g_pos + b*3 + 1), pz = __ldg(g_pos + b*3 + 2);
    float lox = __ldg(g_aabb + b*6 + 0), loy = __ldg(g_aabb + b*6 + 1), loz = __ldg(g_aabb + b*6 + 2);
    float hix = __ldg(g_aabb + b*6 + 3), hiy = __ldg(g_aabb + b*6 + 4), hiz = __ldg(g_aabb + b*6 + 5);

    // voxel center for this lane's sample (meshgrid 'ij': n = i*64 + j*8 + k)
    float ci = (float)(idx >> 6)       + 0.5f;
    float cj = (float)((idx >> 3) & 7) + 0.5f;
    float ck = (float)(idx & 7)        + 0.5f;
    float vx = (ci * 0.125f) * (hix - lox) + lox;
    float vy = (cj * 0.125f) * (hiy - loy) + loy;
    float vz = (ck * 0.125f) * (hiz - loz) + loz;

    float pk0 = r00*vx + r01*vy + r02*vz + px;
    float pk1 = r10*vx + r11*vy + r12*vz + py;
    float pk2 = r20*vx + r21*vy + r22*vz + pz;
    float e = expf(__ldg(g_pls));

    // ---- layer 1: 79x16 GEMV with packed f32x2 FMA ----
    u64 h[8];
    #pragma unroll
    for (int t = 0; t < 8; t++) h[t] = *(const u64*)(s_b1 + 2*t);

    acc_row(h, pk0, s_w1 + 0*16);
    acc_row(h, pk1, s_w1 + 1*16);
    acc_row(h, pk2, s_w1 + 2*16);
    const float* myrow = sz + lane*65;
    #pragma unroll
    for (int kk = 0; kk < 64; kk++) acc_row(h, myrow[kk], s_w1 + (3 + kk)*16);
    acc_row(h, px*e, s_w1 + 67*16);
    acc_row(h, py*e, s_w1 + 68*16);
    acc_row(h, pz*e, s_w1 + 69*16);
    acc_row(h, r00, s_w1 + 70*16);
    acc_row(h, r01, s_w1 + 71*16);
    acc_row(h, r02, s_w1 + 72*16);
    acc_row(h, r10, s_w1 + 73*16);
    acc_row(h, r11, s_w1 + 74*16);
    acc_row(h, r12, s_w1 + 75*16);
    acc_row(h, r20, s_w1 + 76*16);
    acc_row(h, r21, s_w1 + 77*16);
    acc_row(h, r22, s_w1 + 78*16);

    // relu + LN(16) per lane, x2, then sum over the 32 samples (butterfly)
    float v[16];
    #pragma unroll
    for (int t = 0; t < 8; t++) upk2(h[t], v[2*t], v[2*t+1]);
    float m = 0.f;
    #pragma unroll
    for (int j = 0; j < 16; j++){ v[j] = fmaxf(v[j], 0.f); m += v[j]; }
    m *= 0.0625f;
    float var = 0.f;
    #pragma unroll
    for (int j = 0; j < 16; j++){ float d = v[j] - m; var += d*d; }
    var *= 0.0625f;
    float is = rsqrtf(var + 1e-6f);
    #pragma unroll
    for (int j = 0; j < 16; j++){
        float y = (v[j] - m) * is * s_g1[j] + s_be1[j];
        y += y;                                  // z = z + z
        y += __shfl_xor_sync(FULL, y, 16);
        y += __shfl_xor_sync(FULL, y, 8);
        y += __shfl_xor_sync(FULL, y, 4);
        y += __shfl_xor_sync(FULL, y, 2);
        y += __shfl_xor_sync(FULL, y, 1);
        v[j] = y;                                // all lanes hold the sample-sum
    }

    // ---- head: lane = channel ----
    float a = __ldg(g_b2a + lane);
    #pragma unroll
    for (int i = 0; i < 16; i++) a = fmaf(v[i], __ldg(g_w2a + i*32 + lane), a);
    a = fmaxf(a, 0.f);
    float ma = wsum(a) * 0.03125f;
    float da = a - ma;
    float va = wsum(da*da) * 0.03125f;
    float ya = da * rsqrtf(va + 1e-6f) * __ldg(g_g2a + lane) + __ldg(g_be2a + lane);

    float c = __ldg(g_b2b + lane);
    #pragma unroll
    for (int i = 0; i < 32; i++)
        c = fmaf(__shfl_sync(FULL, ya, i), __ldg(g_w2b + i*32 + lane), c);
    c = fmaxf(c, 0.f);
    float mc = wsum(c) * 0.03125f;
    float dc = c - mc;
    float vc = wsum(dc*dc) * 0.03125f;
    float yb = dc * rsqrtf(vc + 1e-6f) * __ldg(g_g2b + lane) + __ldg(g_be2b + lane);
    float zf = yb + ya;   // residual

    float o = (lane < 13) ? __ldg(g_bout + lane) : 0.f;
    #pragma unroll
    for (int i = 0; i < 32; i++){
        float zi = __shfl_sync(FULL, zf, i);
        if (lane < 13) o = fmaf(zi, __ldg(g_wout + i*13 + lane), o);
    }
    if (lane < 13) g_out[b*13 + lane] = tanhf(o);
}

extern "C" void kernel_launch(void* const* d_in, const int* in_sizes, int n_in,
                              void* d_out, int out_size)
{
    (void)in_sizes; (void)n_in; (void)out_size;
    plane_kernel<<<2048, 128>>>(
        (const float*)d_in[0],  (const float*)d_in[1],  (const float*)d_in[2],
        (const float*)d_in[3],  (const int*)  d_in[4],  (const float*)d_in[5],
        (const float*)d_in[6],  (const float*)d_in[7],  (const float*)d_in[8],
        (const float*)d_in[9],  (const float*)d_in[10], (const float*)d_in[11],
        (const float*)d_in[12], (const float*)d_in[13], (const float*)d_in[14],
        (const float*)d_in[15], (const float*)d_in[16], (const float*)d_in[17],
        (const float*)d_in[18], (const float*)d_in[19],
        (float*)d_out);
}